// round 3
// baseline (speedup 1.0000x reference)
#include <cuda_runtime.h>
#include <cstdint>
#include <cstddef>

#define B_TOTAL 65536
#define NGRAPH  64
#define NNODES  2048
#define NEDGES  16384
#define META    64
#define TXD     8
#define NOISE   128
#define RROWS   32    // rows per block in main kernel (16 row-pairs)
#define NFEAT   41    // chain(1) + trig(32) + tx(8)
#define SPAD    36    // padded row stride (floats)
#define ESPLIT  8     // edge splits per graph

typedef unsigned long long ull;

// Scratch
__device__ float g_go[NGRAPH * NOISE];        // per-graph output contribution (+emb_b)
__device__ float deg_all[NGRAPH * NNODES];    // degree, then dinv
__device__ float agg_all[NGRAPH * NNODES];    // raw GCN aggregate (pre w,b)

// ---------- f32x2 helpers ----------
__device__ __forceinline__ ull pack2(float lo, float hi) {
    ull r; asm("mov.b64 %0, {%1,%2};" : "=l"(r) : "f"(lo), "f"(hi)); return r;
}
__device__ __forceinline__ ull fma2(ull a, ull b, ull c) {
    ull d; asm("fma.rn.f32x2 %0, %1, %2, %3;" : "=l"(d) : "l"(a), "l"(b), "l"(c)); return d;
}
__device__ __forceinline__ void unpack2(ull v, float& lo, float& hi) {
    asm("mov.b64 {%0,%1}, %2;" : "=f"(lo), "=f"(hi) : "l"(v));
}

// ============================================================================
// GCN stage kernels (wide, throughput-bound)
// ============================================================================
__global__ __launch_bounds__(256) void k_init(const float* __restrict__ embb) {
    int i = blockIdx.x * 256 + threadIdx.x;
    if (i < NGRAPH * NNODES) deg_all[i] = 1.0f;          // self loop
    if (i < NGRAPH * NOISE)  g_go[i] = embb[i & (NOISE - 1)];
}

// deg accumulation: 64 graphs x ESPLIT blocks, int4 loads of dst, REDG adds.
__global__ __launch_bounds__(256) void k_deg(const int* __restrict__ edges) {
    const int g  = blockIdx.x >> 3;
    const int sp = blockIdx.x & 7;
    const int4* dst4 = reinterpret_cast<const int4*>(
        edges + (size_t)g * 2 * NEDGES + NEDGES) + sp * (NEDGES / ESPLIT / 4);
    float* deg = deg_all + (size_t)g * NNODES;
    #pragma unroll
    for (int i = 0; i < NEDGES / ESPLIT / 4 / 256; i++) {
        int4 d = __ldg(&dst4[i * 256 + threadIdx.x]);
        atomicAdd(&deg[d.x], 1.0f);
        atomicAdd(&deg[d.y], 1.0f);
        atomicAdd(&deg[d.z], 1.0f);
        atomicAdd(&deg[d.w], 1.0f);
    }
}

// dinv = rsqrt(deg) (in place); agg init = dinv^2 (self-loop term)
__global__ __launch_bounds__(256) void k_dinv() {
    int i = blockIdx.x * 256 + threadIdx.x;
    float dv = rsqrtf(deg_all[i]);
    deg_all[i] = dv;
    agg_all[i] = dv * dv;
}

// norm pass: agg[dst] += dinv[src]*dinv[dst]
__global__ __launch_bounds__(256) void k_norm(const int* __restrict__ edges) {
    const int g  = blockIdx.x >> 3;
    const int sp = blockIdx.x & 7;
    const int* base = edges + (size_t)g * 2 * NEDGES;
    const int4* src4 = reinterpret_cast<const int4*>(base) + sp * (NEDGES / ESPLIT / 4);
    const int4* dst4 = reinterpret_cast<const int4*>(base + NEDGES) + sp * (NEDGES / ESPLIT / 4);
    const float* dinv = deg_all + (size_t)g * NNODES;
    float* agg = agg_all + (size_t)g * NNODES;
    #pragma unroll
    for (int i = 0; i < NEDGES / ESPLIT / 4 / 256; i++) {
        int4 s = __ldg(&src4[i * 256 + threadIdx.x]);
        int4 d = __ldg(&dst4[i * 256 + threadIdx.x]);
        float sx = __ldg(&dinv[s.x]), sy = __ldg(&dinv[s.y]);
        float sz = __ldg(&dinv[s.z]), sw = __ldg(&dinv[s.w]);
        float dx = __ldg(&dinv[d.x]), dy = __ldg(&dinv[d.y]);
        float dz = __ldg(&dinv[d.z]), dw = __ldg(&dinv[d.w]);
        atomicAdd(&agg[d.x], sx * dx);
        atomicAdd(&agg[d.y], sy * dy);
        atomicAdd(&agg[d.z], sz * dz);
        atomicAdd(&agg[d.w], sw * dw);
    }
}

// g_go += w * (AGG @ embW_slice) + b * colsum(embW_slice)
// grid = 128 blocks = 16 K-splits x 8 graph-splits; 128 threads (col = tid).
__global__ __launch_bounds__(128) void gcn_gemm(
    const float* __restrict__ embW, const float* __restrict__ gwp,
    const float* __restrict__ gbp)
{
    __shared__ float aggs[8][128];
    const int tid = threadIdx.x;
    const int ks  = blockIdx.x & 15;
    const int gsp = blockIdx.x >> 4;

    #pragma unroll
    for (int j = 0; j < 8; j++)
        aggs[j][tid] = agg_all[(size_t)(gsp * 8 + j) * NNODES + ks * 128 + tid];
    __syncthreads();

    float acc[8] = {0.f, 0.f, 0.f, 0.f, 0.f, 0.f, 0.f, 0.f};
    float wsum = 0.f;
    const float* wb = embW + (size_t)ks * 128 * NOISE + tid;
    #pragma unroll 4
    for (int n = 0; n < 128; n++) {
        float wv = __ldg(wb + (size_t)n * NOISE);
        wsum += wv;
        #pragma unroll
        for (int j = 0; j < 8; j++)
            acc[j] = fmaf(aggs[j][n], wv, acc[j]);
    }
    const float w = gwp[0], b = gbp[0];
    const float bterm = b * wsum;
    #pragma unroll
    for (int j = 0; j < 8; j++)
        atomicAdd(&g_go[(gsp * 8 + j) * NOISE + tid], fmaf(w, acc[j], bterm));
}

// ============================================================================
// Kernel 2: fused trig-MLP + output GEMM (unchanged from R2 retile).
// ============================================================================
__global__ __launch_bounds__(128) void noise_main(
    const int*   __restrict__ gid,   const float* __restrict__ chain,
    const float* __restrict__ td,    const float* __restrict__ tx,
    const float* __restrict__ trigW, const float* __restrict__ trigb,
    const float* __restrict__ embW,  float* __restrict__ out)
{
    __shared__ __align__(16) float td_s[META][SPAD];
    __shared__ __align__(16) float feat_s[NFEAT][SPAD];  // 0=chain,1..32=trig,33..40=tx
    __shared__ int gs[RROWS];

    const int tid = threadIdx.x;
    const int r0  = blockIdx.x * RROWS;

    // ---- stage inputs (transposed) ----
    {
        const float4* tdg = reinterpret_cast<const float4*>(td + (size_t)r0 * META);
        for (int i = tid; i < RROWS * (META / 4); i += 128) {
            float4 v = tdg[i];
            int r = i / (META / 4);
            int m = (i % (META / 4)) * 4;
            td_s[m + 0][r] = v.x; td_s[m + 1][r] = v.y;
            td_s[m + 2][r] = v.z; td_s[m + 3][r] = v.w;
        }
        const float4* txg = reinterpret_cast<const float4*>(tx + (size_t)r0 * TXD);
        for (int i = tid; i < RROWS * (TXD / 4); i += 128) {
            float4 v = txg[i];
            int r = i / (TXD / 4);
            int m = (i % (TXD / 4)) * 4;
            feat_s[33 + m + 0][r] = v.x; feat_s[33 + m + 1][r] = v.y;
            feat_s[33 + m + 2][r] = v.z; feat_s[33 + m + 3][r] = v.w;
        }
        if (tid < RROWS) {
            feat_s[0][tid] = chain[r0 + tid];
            gs[tid] = gid[r0 + tid];
        }
    }
    __syncthreads();

    // ---- phase 1: trig = relu(td @ trig_W + trig_b), row-paired ----
    {
        const int k = tid & 31;
        const int w = tid >> 5;
        float tb = __ldg(&trigb[k]);
        ull acc0 = pack2(tb, tb), acc1 = acc0, acc2 = acc0, acc3 = acc0;
        #pragma unroll 16
        for (int m = 0; m < META; m++) {
            float wv = __ldg(&trigW[m * 32 + k]);
            ull wd = pack2(wv, wv);
            ull t0 = *reinterpret_cast<const ull*>(&td_s[m][2 * (w)]);
            ull t1 = *reinterpret_cast<const ull*>(&td_s[m][2 * (w + 4)]);
            ull t2 = *reinterpret_cast<const ull*>(&td_s[m][2 * (w + 8)]);
            ull t3 = *reinterpret_cast<const ull*>(&td_s[m][2 * (w + 12)]);
            acc0 = fma2(wd, t0, acc0);
            acc1 = fma2(wd, t1, acc1);
            acc2 = fma2(wd, t2, acc2);
            acc3 = fma2(wd, t3, acc3);
        }
        float a, b2;
        unpack2(acc0, a, b2);
        *reinterpret_cast<ull*>(&feat_s[1 + k][2 * (w)])      = pack2(fmaxf(a, 0.f), fmaxf(b2, 0.f));
        unpack2(acc1, a, b2);
        *reinterpret_cast<ull*>(&feat_s[1 + k][2 * (w + 4)])  = pack2(fmaxf(a, 0.f), fmaxf(b2, 0.f));
        unpack2(acc2, a, b2);
        *reinterpret_cast<ull*>(&feat_s[1 + k][2 * (w + 8)])  = pack2(fmaxf(a, 0.f), fmaxf(b2, 0.f));
        unpack2(acc3, a, b2);
        *reinterpret_cast<ull*>(&feat_s[1 + k][2 * (w + 12)]) = pack2(fmaxf(a, 0.f), fmaxf(b2, 0.f));
    }
    __syncthreads();

    // ---- phase 2: output GEMM over 41 features ----
    {
        const int jq = tid & 31;          // cols 4*jq..4*jq+3
        const int w  = tid >> 5;          // pairs 4w..4w+3

        ull acc[4][4];
        #pragma unroll
        for (int pi = 0; pi < 4; pi++) {
            int p  = 4 * w + pi;
            int ra = 2 * p, rb = ra + 1;
            const float4 ga4 = __ldg(reinterpret_cast<const float4*>(
                &g_go[gs[ra] * NOISE + 4 * jq]));
            const float4 gb4 = __ldg(reinterpret_cast<const float4*>(
                &g_go[gs[rb] * NOISE + 4 * jq]));
            acc[pi][0] = pack2(ga4.x, gb4.x);
            acc[pi][1] = pack2(ga4.y, gb4.y);
            acc[pi][2] = pack2(ga4.z, gb4.z);
            acc[pi][3] = pack2(ga4.w, gb4.w);
        }

        const float4* wrow = reinterpret_cast<const float4*>(embW + (size_t)2048 * NOISE) + jq;
        #pragma unroll 4
        for (int k = 0; k < NFEAT; k++) {
            float4 wv = __ldg(wrow + (size_t)k * (NOISE / 4));
            ull wd0 = pack2(wv.x, wv.x);
            ull wd1 = pack2(wv.y, wv.y);
            ull wd2 = pack2(wv.z, wv.z);
            ull wd3 = pack2(wv.w, wv.w);
            ulonglong2 t01 = *reinterpret_cast<const ulonglong2*>(&feat_s[k][8 * w]);
            ulonglong2 t23 = *reinterpret_cast<const ulonglong2*>(&feat_s[k][8 * w + 4]);
            acc[0][0] = fma2(wd0, t01.x, acc[0][0]);
            acc[0][1] = fma2(wd1, t01.x, acc[0][1]);
            acc[0][2] = fma2(wd2, t01.x, acc[0][2]);
            acc[0][3] = fma2(wd3, t01.x, acc[0][3]);
            acc[1][0] = fma2(wd0, t01.y, acc[1][0]);
            acc[1][1] = fma2(wd1, t01.y, acc[1][1]);
            acc[1][2] = fma2(wd2, t01.y, acc[1][2]);
            acc[1][3] = fma2(wd3, t01.y, acc[1][3]);
            acc[2][0] = fma2(wd0, t23.x, acc[2][0]);
            acc[2][1] = fma2(wd1, t23.x, acc[2][1]);
            acc[2][2] = fma2(wd2, t23.x, acc[2][2]);
            acc[2][3] = fma2(wd3, t23.x, acc[2][3]);
            acc[3][0] = fma2(wd0, t23.y, acc[3][0]);
            acc[3][1] = fma2(wd1, t23.y, acc[3][1]);
            acc[3][2] = fma2(wd2, t23.y, acc[3][2]);
            acc[3][3] = fma2(wd3, t23.y, acc[3][3]);
        }

        #pragma unroll
        for (int pi = 0; pi < 4; pi++) {
            int p  = 4 * w + pi;
            size_t ra = (size_t)(r0 + 2 * p);
            float4 lo, hi;
            unpack2(acc[pi][0], lo.x, hi.x);
            unpack2(acc[pi][1], lo.y, hi.y);
            unpack2(acc[pi][2], lo.z, hi.z);
            unpack2(acc[pi][3], lo.w, hi.w);
            *reinterpret_cast<float4*>(out + ra * NOISE + 4 * jq)       = lo;
            *reinterpret_cast<float4*>(out + (ra + 1) * NOISE + 4 * jq) = hi;
        }
    }
}

// ============================================================================
extern "C" void kernel_launch(void* const* d_in, const int* in_sizes, int n_in,
                              void* d_out, int out_size) {
    (void)in_sizes; (void)n_in; (void)out_size;
    const int*   gid   = (const int*)  d_in[0];
    const float* chain = (const float*)d_in[1];
    const float* td    = (const float*)d_in[2];
    const float* tx    = (const float*)d_in[3];
    const int*   edges = (const int*)  d_in[4];
    const float* gw    = (const float*)d_in[5];
    const float* gb    = (const float*)d_in[6];
    const float* trigW = (const float*)d_in[7];
    const float* trigb = (const float*)d_in[8];
    const float* embW  = (const float*)d_in[9];
    const float* embb  = (const float*)d_in[10];
    float* out = (float*)d_out;

    k_init<<<(NGRAPH * NNODES + 255) / 256, 256>>>(embb);
    k_deg<<<NGRAPH * ESPLIT, 256>>>(edges);
    k_dinv<<<NGRAPH * NNODES / 256, 256>>>();
    k_norm<<<NGRAPH * ESPLIT, 256>>>(edges);
    gcn_gemm<<<128, 128>>>(embW, gw, gb);
    noise_main<<<B_TOTAL / RROWS, 128>>>(gid, chain, td, tx, trigW, trigb, embW, out);
}

// round 4
// speedup vs baseline: 1.0725x; 1.0725x over previous
#include <cuda_runtime.h>
#include <cstdint>
#include <cstddef>

#define B_TOTAL 65536
#define NGRAPH  64
#define NNODES  2048
#define NEDGES  16384
#define META    64
#define TXD     8
#define NOISE   128
#define RROWS   32    // rows per block in main kernel (16 row-pairs)
#define NFEAT   41    // chain(1) + trig(32) + tx(8)
#define SPAD    36    // padded row stride (floats)
#define ESPLIT  8     // edge splits per graph

typedef unsigned long long ull;

// Fused zero-init scratch: [deg_all | agg_all | g_go]
#define SCRATCH_FLOATS (NGRAPH * NNODES * 2 + NGRAPH * NOISE)
__device__ float scratch[SCRATCH_FLOATS];
#define DEG_ALL (scratch)
#define AGG_ALL (scratch + NGRAPH * NNODES)
#define G_GO    (scratch + 2 * NGRAPH * NNODES)

// ---------- f32x2 helpers ----------
__device__ __forceinline__ ull pack2(float lo, float hi) {
    ull r; asm("mov.b64 %0, {%1,%2};" : "=l"(r) : "f"(lo), "f"(hi)); return r;
}
__device__ __forceinline__ ull fma2(ull a, ull b, ull c) {
    ull d; asm("fma.rn.f32x2 %0, %1, %2, %3;" : "=l"(d) : "l"(a), "l"(b), "l"(c)); return d;
}
__device__ __forceinline__ void unpack2(ull v, float& lo, float& hi) {
    asm("mov.b64 {%0,%1}, %2;" : "=f"(lo), "=f"(hi) : "l"(v));
}

// ============================================================================
// k_deg: incoming-edge counts (deg = count; true degree = count+1).
// 512 blocks = 64 graphs x 8 splits, 8 edges/thread via 2x int4, REDG adds.
// ============================================================================
__global__ __launch_bounds__(256) void k_deg(const int* __restrict__ edges) {
    const int g  = blockIdx.x >> 3;
    const int sp = blockIdx.x & 7;
    const int4* dst4 = reinterpret_cast<const int4*>(
        edges + (size_t)g * 2 * NEDGES + NEDGES) + sp * (NEDGES / ESPLIT / 4);
    float* deg = DEG_ALL + (size_t)g * NNODES;
    int4 d0 = __ldg(&dst4[threadIdx.x]);
    int4 d1 = __ldg(&dst4[256 + threadIdx.x]);
    atomicAdd(&deg[d0.x], 1.0f);
    atomicAdd(&deg[d0.y], 1.0f);
    atomicAdd(&deg[d0.z], 1.0f);
    atomicAdd(&deg[d0.w], 1.0f);
    atomicAdd(&deg[d1.x], 1.0f);
    atomicAdd(&deg[d1.y], 1.0f);
    atomicAdd(&deg[d1.z], 1.0f);
    atomicAdd(&deg[d1.w], 1.0f);
}

// ============================================================================
// k_norm: agg[dst] += dinv[src]*dinv[dst], with dinv staged in smem per block.
// 512 blocks = 64 graphs x 8 splits. Gathers are LDS, accumulate via REDG.
// ============================================================================
__global__ __launch_bounds__(256) void k_norm(const int* __restrict__ edges) {
    __shared__ float dinv_s[NNODES];
    const int g  = blockIdx.x >> 3;
    const int sp = blockIdx.x & 7;
    const int tid = threadIdx.x;

    const float* deg = DEG_ALL + (size_t)g * NNODES;
    #pragma unroll
    for (int i = 0; i < NNODES / 256; i++)
        dinv_s[i * 256 + tid] = rsqrtf(deg[i * 256 + tid] + 1.0f);
    __syncthreads();

    const int* base = edges + (size_t)g * 2 * NEDGES;
    const int4* src4 = reinterpret_cast<const int4*>(base) + sp * (NEDGES / ESPLIT / 4);
    const int4* dst4 = reinterpret_cast<const int4*>(base + NEDGES) + sp * (NEDGES / ESPLIT / 4);
    float* agg = AGG_ALL + (size_t)g * NNODES;

    #pragma unroll
    for (int i = 0; i < 2; i++) {
        int4 s = __ldg(&src4[i * 256 + tid]);
        int4 d = __ldg(&dst4[i * 256 + tid]);
        float vx = dinv_s[s.x] * dinv_s[d.x];
        float vy = dinv_s[s.y] * dinv_s[d.y];
        float vz = dinv_s[s.z] * dinv_s[d.z];
        float vw = dinv_s[s.w] * dinv_s[d.w];
        atomicAdd(&agg[d.x], vx);
        atomicAdd(&agg[d.y], vy);
        atomicAdd(&agg[d.z], vz);
        atomicAdd(&agg[d.w], vw);
    }
}

// ============================================================================
// gcn_gemm: g_go += w * ((AGG + dinv^2) @ embW_slice) + b * colsum(embW_slice)
// 128 blocks = 16 K-splits x 8 graph-splits; 128 threads (col = tid).
// Self-loop dinv^2 term folded here (dinv recomputed from deg).
// ============================================================================
__global__ __launch_bounds__(128) void gcn_gemm(
    const float* __restrict__ embW, const float* __restrict__ gwp,
    const float* __restrict__ gbp)
{
    __shared__ float aggs[8][128];
    const int tid = threadIdx.x;
    const int ks  = blockIdx.x & 15;
    const int gsp = blockIdx.x >> 4;

    #pragma unroll
    for (int j = 0; j < 8; j++) {
        size_t idx = (size_t)(gsp * 8 + j) * NNODES + ks * 128 + tid;
        float r = rsqrtf(DEG_ALL[idx] + 1.0f);
        aggs[j][tid] = AGG_ALL[idx] + r * r;
    }
    __syncthreads();

    float acc[8] = {0.f, 0.f, 0.f, 0.f, 0.f, 0.f, 0.f, 0.f};
    float wsum = 0.f;
    const float* wb = embW + (size_t)ks * 128 * NOISE + tid;
    #pragma unroll 8
    for (int n = 0; n < 128; n++) {
        float wv = __ldg(wb + (size_t)n * NOISE);
        wsum += wv;
        #pragma unroll
        for (int j = 0; j < 8; j++)
            acc[j] = fmaf(aggs[j][n], wv, acc[j]);
    }
    const float w = gwp[0], b = gbp[0];
    const float bterm = b * wsum;
    #pragma unroll
    for (int j = 0; j < 8; j++)
        atomicAdd(&G_GO[(gsp * 8 + j) * NOISE + tid], fmaf(w, acc[j], bterm));
}

// ============================================================================
// noise_main: fused trig-MLP + output GEMM (emb_b folded into acc init).
// ============================================================================
__global__ __launch_bounds__(128) void noise_main(
    const int*   __restrict__ gid,   const float* __restrict__ chain,
    const float* __restrict__ td,    const float* __restrict__ tx,
    const float* __restrict__ trigW, const float* __restrict__ trigb,
    const float* __restrict__ embW,  const float* __restrict__ embb,
    float* __restrict__ out)
{
    __shared__ __align__(16) float td_s[META][SPAD];
    __shared__ __align__(16) float feat_s[NFEAT][SPAD];  // 0=chain,1..32=trig,33..40=tx
    __shared__ int gs[RROWS];

    const int tid = threadIdx.x;
    const int r0  = blockIdx.x * RROWS;

    // ---- stage inputs (transposed) ----
    {
        const float4* tdg = reinterpret_cast<const float4*>(td + (size_t)r0 * META);
        for (int i = tid; i < RROWS * (META / 4); i += 128) {
            float4 v = tdg[i];
            int r = i / (META / 4);
            int m = (i % (META / 4)) * 4;
            td_s[m + 0][r] = v.x; td_s[m + 1][r] = v.y;
            td_s[m + 2][r] = v.z; td_s[m + 3][r] = v.w;
        }
        const float4* txg = reinterpret_cast<const float4*>(tx + (size_t)r0 * TXD);
        for (int i = tid; i < RROWS * (TXD / 4); i += 128) {
            float4 v = txg[i];
            int r = i / (TXD / 4);
            int m = (i % (TXD / 4)) * 4;
            feat_s[33 + m + 0][r] = v.x; feat_s[33 + m + 1][r] = v.y;
            feat_s[33 + m + 2][r] = v.z; feat_s[33 + m + 3][r] = v.w;
        }
        if (tid < RROWS) {
            feat_s[0][tid] = chain[r0 + tid];
            gs[tid] = gid[r0 + tid];
        }
    }
    __syncthreads();

    // ---- phase 1: trig = relu(td @ trig_W + trig_b), row-paired ----
    {
        const int k = tid & 31;
        const int w = tid >> 5;
        float tb = __ldg(&trigb[k]);
        ull acc0 = pack2(tb, tb), acc1 = acc0, acc2 = acc0, acc3 = acc0;
        #pragma unroll 16
        for (int m = 0; m < META; m++) {
            float wv = __ldg(&trigW[m * 32 + k]);
            ull wd = pack2(wv, wv);
            ull t0 = *reinterpret_cast<const ull*>(&td_s[m][2 * (w)]);
            ull t1 = *reinterpret_cast<const ull*>(&td_s[m][2 * (w + 4)]);
            ull t2 = *reinterpret_cast<const ull*>(&td_s[m][2 * (w + 8)]);
            ull t3 = *reinterpret_cast<const ull*>(&td_s[m][2 * (w + 12)]);
            acc0 = fma2(wd, t0, acc0);
            acc1 = fma2(wd, t1, acc1);
            acc2 = fma2(wd, t2, acc2);
            acc3 = fma2(wd, t3, acc3);
        }
        float a, b2;
        unpack2(acc0, a, b2);
        *reinterpret_cast<ull*>(&feat_s[1 + k][2 * (w)])      = pack2(fmaxf(a, 0.f), fmaxf(b2, 0.f));
        unpack2(acc1, a, b2);
        *reinterpret_cast<ull*>(&feat_s[1 + k][2 * (w + 4)])  = pack2(fmaxf(a, 0.f), fmaxf(b2, 0.f));
        unpack2(acc2, a, b2);
        *reinterpret_cast<ull*>(&feat_s[1 + k][2 * (w + 8)])  = pack2(fmaxf(a, 0.f), fmaxf(b2, 0.f));
        unpack2(acc3, a, b2);
        *reinterpret_cast<ull*>(&feat_s[1 + k][2 * (w + 12)]) = pack2(fmaxf(a, 0.f), fmaxf(b2, 0.f));
    }
    __syncthreads();

    // ---- phase 2: output GEMM over 41 features ----
    {
        const int jq = tid & 31;          // cols 4*jq..4*jq+3
        const int w  = tid >> 5;          // pairs 4w..4w+3

        const float4 eb = __ldg(reinterpret_cast<const float4*>(&embb[4 * jq]));

        ull acc[4][4];
        #pragma unroll
        for (int pi = 0; pi < 4; pi++) {
            int p  = 4 * w + pi;
            int ra = 2 * p, rb = ra + 1;
            const float4 ga4 = __ldg(reinterpret_cast<const float4*>(
                &G_GO[gs[ra] * NOISE + 4 * jq]));
            const float4 gb4 = __ldg(reinterpret_cast<const float4*>(
                &G_GO[gs[rb] * NOISE + 4 * jq]));
            acc[pi][0] = pack2(ga4.x + eb.x, gb4.x + eb.x);
            acc[pi][1] = pack2(ga4.y + eb.y, gb4.y + eb.y);
            acc[pi][2] = pack2(ga4.z + eb.z, gb4.z + eb.z);
            acc[pi][3] = pack2(ga4.w + eb.w, gb4.w + eb.w);
        }

        const float4* wrow = reinterpret_cast<const float4*>(embW + (size_t)2048 * NOISE) + jq;
        #pragma unroll 4
        for (int k = 0; k < NFEAT; k++) {
            float4 wv = __ldg(wrow + (size_t)k * (NOISE / 4));
            ull wd0 = pack2(wv.x, wv.x);
            ull wd1 = pack2(wv.y, wv.y);
            ull wd2 = pack2(wv.z, wv.z);
            ull wd3 = pack2(wv.w, wv.w);
            ulonglong2 t01 = *reinterpret_cast<const ulonglong2*>(&feat_s[k][8 * w]);
            ulonglong2 t23 = *reinterpret_cast<const ulonglong2*>(&feat_s[k][8 * w + 4]);
            acc[0][0] = fma2(wd0, t01.x, acc[0][0]);
            acc[0][1] = fma2(wd1, t01.x, acc[0][1]);
            acc[0][2] = fma2(wd2, t01.x, acc[0][2]);
            acc[0][3] = fma2(wd3, t01.x, acc[0][3]);
            acc[1][0] = fma2(wd0, t01.y, acc[1][0]);
            acc[1][1] = fma2(wd1, t01.y, acc[1][1]);
            acc[1][2] = fma2(wd2, t01.y, acc[1][2]);
            acc[1][3] = fma2(wd3, t01.y, acc[1][3]);
            acc[2][0] = fma2(wd0, t23.x, acc[2][0]);
            acc[2][1] = fma2(wd1, t23.x, acc[2][1]);
            acc[2][2] = fma2(wd2, t23.x, acc[2][2]);
            acc[2][3] = fma2(wd3, t23.x, acc[2][3]);
            acc[3][0] = fma2(wd0, t23.y, acc[3][0]);
            acc[3][1] = fma2(wd1, t23.y, acc[3][1]);
            acc[3][2] = fma2(wd2, t23.y, acc[3][2]);
            acc[3][3] = fma2(wd3, t23.y, acc[3][3]);
        }

        #pragma unroll
        for (int pi = 0; pi < 4; pi++) {
            int p  = 4 * w + pi;
            size_t ra = (size_t)(r0 + 2 * p);
            float4 lo, hi;
            unpack2(acc[pi][0], lo.x, hi.x);
            unpack2(acc[pi][1], lo.y, hi.y);
            unpack2(acc[pi][2], lo.z, hi.z);
            unpack2(acc[pi][3], lo.w, hi.w);
            *reinterpret_cast<float4*>(out + ra * NOISE + 4 * jq)       = lo;
            *reinterpret_cast<float4*>(out + (ra + 1) * NOISE + 4 * jq) = hi;
        }
    }
}

// ============================================================================
extern "C" void kernel_launch(void* const* d_in, const int* in_sizes, int n_in,
                              void* d_out, int out_size) {
    (void)in_sizes; (void)n_in; (void)out_size;
    const int*   gid   = (const int*)  d_in[0];
    const float* chain = (const float*)d_in[1];
    const float* td    = (const float*)d_in[2];
    const float* tx    = (const float*)d_in[3];
    const int*   edges = (const int*)  d_in[4];
    const float* gw    = (const float*)d_in[5];
    const float* gb    = (const float*)d_in[6];
    const float* trigW = (const float*)d_in[7];
    const float* trigb = (const float*)d_in[8];
    const float* embW  = (const float*)d_in[9];
    const float* embb  = (const float*)d_in[10];
    float* out = (float*)d_out;

    void* scratch_ptr = nullptr;
    cudaGetSymbolAddress(&scratch_ptr, scratch);
    cudaMemsetAsync(scratch_ptr, 0, SCRATCH_FLOATS * sizeof(float));

    k_deg<<<NGRAPH * ESPLIT, 256>>>(edges);
    k_norm<<<NGRAPH * ESPLIT, 256>>>(edges);
    gcn_gemm<<<128, 128>>>(embW, gw, gb);
    noise_main<<<B_TOTAL / RROWS, 128>>>(gid, chain, td, tx, trigW, trigb, embW, embb, out);
}